// round 16
// baseline (speedup 1.0000x reference)
#include <cuda_runtime.h>
#include <cuda_bf16.h>
#include <cstdint>
#include <cstddef>

typedef __nv_bfloat16 bf16;

// Problem constants
#define Bq   2
#define Nt   8192
#define Dd   1024
#define Hh   16
#define DH   64
#define Mrows (Bq * Nt)

// ---------------- scratch ---------------------------------------------------
__device__ bf16  g_xh[(size_t)Mrows * Dd];
__device__ bf16  g_xl[(size_t)Mrows * Dd];
__device__ bf16  g_wth[(size_t)Dd * Dd];
__device__ bf16  g_wtl[(size_t)Dd * Dd];
__device__ bf16  g_wvh[(size_t)Dd * Dd];
__device__ bf16  g_wvl[(size_t)Dd * Dd];
// fp32 atomic arena: Sf (2M f) | NTf (2M f) | Gr (131072 f)
#define SF_OFF  0
#define NTF_OFF ((size_t)Bq * Dd * Dd)
#define GR_OFF  (2 * (size_t)Bq * Dd * Dd)
#define ACC_TOT (2 * (size_t)Bq * Dd * Dd + (size_t)Bq * Hh * DH * DH)
__device__ float g_acc[ACC_TOT];
__device__ bf16  g_sh [(size_t)Bq * Dd * Dd];
__device__ bf16  g_sl [(size_t)Bq * Dd * Dd];
__device__ bf16  g_ph [(size_t)Bq * Dd * Dd];
__device__ bf16  g_pl [(size_t)Bq * Dd * Dd];
__device__ bf16  g_mth[(size_t)Bq * Dd * Dd];
__device__ bf16  g_mtl[(size_t)Bq * Dd * Dd];
__device__ bf16  g_nth[(size_t)Bq * Dd * Dd];
__device__ bf16  g_ntl[(size_t)Bq * Dd * Dd];

// ---------------- PTX helpers -------------------------------------------------
__device__ __forceinline__ uint32_t smem_u32(const void* p) {
    uint32_t a;
    asm("{ .reg .u64 t; cvta.to.shared.u64 t, %1; cvt.u32.u64 %0, t; }"
        : "=r"(a) : "l"(p));
    return a;
}

#define LDM4(r, addr)                                                          \
    asm volatile("ldmatrix.sync.aligned.m8n8.x4.shared.b16 {%0,%1,%2,%3}, [%4];" \
        : "=r"((r)[0]), "=r"((r)[1]), "=r"((r)[2]), "=r"((r)[3]) : "r"(addr))

#define LDM4T(r, addr)                                                         \
    asm volatile("ldmatrix.sync.aligned.m8n8.x4.trans.shared.b16 {%0,%1,%2,%3}, [%4];" \
        : "=r"((r)[0]), "=r"((r)[1]), "=r"((r)[2]), "=r"((r)[3]) : "r"(addr))

__device__ __forceinline__ void mma16(float* c, const uint32_t* a, const uint32_t* b) {
    asm volatile(
        "mma.sync.aligned.m16n8k16.row.col.f32.bf16.bf16.f32 "
        "{%0,%1,%2,%3}, {%4,%5,%6,%7}, {%8,%9}, {%0,%1,%2,%3};"
        : "+f"(c[0]), "+f"(c[1]), "+f"(c[2]), "+f"(c[3])
        : "r"(a[0]), "r"(a[1]), "r"(a[2]), "r"(a[3]), "r"(b[0]), "r"(b[1]));
}

#define CPA(dst, src) \
    asm volatile("cp.async.cg.shared.global [%0], [%1], 16;" :: "r"(dst), "l"(src) : "memory")
#define CPC() asm volatile("cp.async.commit_group;" ::: "memory")
#define CPW(n) asm volatile("cp.async.wait_group %0;" :: "n"(n) : "memory")

#define REDADD(ptr, v) \
    asm volatile("red.global.add.f32 [%0], %1;" :: "l"(ptr), "f"(v) : "memory")

__device__ __forceinline__ uint32_t swz(uint32_t row, uint32_t c) {
    return row * 64u + (((c ^ ((row >> 1) & 3u)) & 3u) << 4);
}
__device__ __forceinline__ uint32_t swz256(uint32_t row, uint32_t c) {
    return row * 256u + (((c ^ (row & 15u)) & 15u) << 4);
}

// ---------------- bf16 split GEMM, 128x128 tile, 256 threads, 2 CTAs/SM --------
// MODE 0: fp32 store; MODE 1: fp32 red.add; MODE 3: split-bf16 store (ld 1024).
#define BK 32
#define PLANE_B 8192
#define STAGE_B (4 * PLANE_B)
#define NSTAGE  3
#define SMB     (NSTAGE * STAGE_B)    // 98304
#define OFF_AL  PLANE_B
#define OFF_BH  (2 * PLANE_B)
#define OFF_BL  (3 * PLANE_B)

template <int MODE>
__global__ __launch_bounds__(256, 2)
void mma_gemm(const bf16* __restrict__ gAh, const bf16* __restrict__ gAl, size_t aZ,
              const bf16* __restrict__ gBh, const bf16* __restrict__ gBl, size_t bZ,
              float* Cf0, float* Cf1, bf16* Ch, bf16* Cl, size_t cZ,
              int nxt, int ksteps)
{
    extern __shared__ __align__(16) char smc[];
    const int z = blockIdx.z;
    const int ks0 = (blockIdx.x / nxt) * ksteps;
    const int bn  = (blockIdx.x % nxt) * 128;
    const bf16* Ah = gAh + (size_t)z * aZ;
    const bf16* Al = gAl + (size_t)z * aZ;
    const bf16* Bh = gBh + (size_t)z * bZ;
    const bf16* Bl = gBl + (size_t)z * bZ;
    float* Cf = z ? Cf1 : Cf0;

    const int bm = blockIdx.y * 128;
    const int tid = threadIdx.x;
    const int wid = tid >> 5;
    const int lid = tid & 31;
    const int g = lid >> 2;
    const int t = lid & 3;
    const int wm = (wid >> 2) * 64;
    const int wn = (wid & 3) * 32;

    const uint32_t sbase = smem_u32(smc);

    const uint32_t rA = (uint32_t)tid >> 2;
    const uint32_t cC = (uint32_t)tid & 3;
    const uint32_t rA1 = rA + 64;
    const uint32_t sw0 = swz(rA, cC);
    const uint32_t sw1 = swz(rA1, cC);
    const bf16* gah0 = Ah + (size_t)(bm + rA) * 1024 + cC * 8;
    const bf16* gah1 = Ah + (size_t)(bm + rA1) * 1024 + cC * 8;
    const bf16* gal0 = Al + (size_t)(bm + rA) * 1024 + cC * 8;
    const bf16* gal1 = Al + (size_t)(bm + rA1) * 1024 + cC * 8;
    const bf16* gbh0 = Bh + (size_t)(bn + rA) * 1024 + cC * 8;
    const bf16* gbh1 = Bh + (size_t)(bn + rA1) * 1024 + cC * 8;
    const bf16* gbl0 = Bl + (size_t)(bn + rA) * 1024 + cC * 8;
    const bf16* gbl1 = Bl + (size_t)(bn + rA1) * 1024 + cC * 8;

    auto issue = [&](int k0, int st) {
        uint32_t sb2 = sbase + (uint32_t)st * STAGE_B;
        CPA(sb2 + sw0,          gah0 + k0);
        CPA(sb2 + sw1,          gah1 + k0);
        CPA(sb2 + OFF_AL + sw0, gal0 + k0);
        CPA(sb2 + OFF_AL + sw1, gal1 + k0);
        CPA(sb2 + OFF_BH + sw0, gbh0 + k0);
        CPA(sb2 + OFF_BH + sw1, gbh1 + k0);
        CPA(sb2 + OFF_BL + sw0, gbl0 + k0);
        CPA(sb2 + OFF_BL + sw1, gbl1 + k0);
    };

    float acc[4][4][4];
    #pragma unroll
    for (int i = 0; i < 4; i++)
        #pragma unroll
        for (int j = 0; j < 4; j++)
            #pragma unroll
            for (int e = 0; e < 4; e++) acc[i][j][e] = 0.0f;

    uint32_t arow[4], brow[2];
    #pragma unroll
    for (int i = 0; i < 4; i++) arow[i] = (uint32_t)(wm + i * 16 + (lid & 15));
    #pragma unroll
    for (int jp = 0; jp < 2; jp++)
        brow[jp] = (uint32_t)(wn + jp * 16 + (lid & 7) + ((lid >> 4) << 3));
    const uint32_t aco = (uint32_t)(lid >> 4);
    const uint32_t bco = (uint32_t)((lid >> 3) & 1);

    auto compute = [&](int buf) {
        const uint32_t bb = sbase + (uint32_t)buf * STAGE_B;
        #pragma unroll
        for (int ks2 = 0; ks2 < 2; ks2++) {
            uint32_t ah[4][4], al[4][4], bh[4][2], bl[4][2];
            #pragma unroll
            for (int i = 0; i < 4; i++) {
                uint32_t off = swz(arow[i], ks2 * 2 + aco);
                LDM4(ah[i], bb + off);
                LDM4(al[i], bb + OFF_AL + off);
            }
            #pragma unroll
            for (int jp = 0; jp < 2; jp++) {
                uint32_t off = swz(brow[jp], ks2 * 2 + bco);
                uint32_t r[4];
                LDM4(r, bb + OFF_BH + off);
                bh[2 * jp][0] = r[0]; bh[2 * jp][1] = r[1];
                bh[2 * jp + 1][0] = r[2]; bh[2 * jp + 1][1] = r[3];
                LDM4(r, bb + OFF_BL + off);
                bl[2 * jp][0] = r[0]; bl[2 * jp][1] = r[1];
                bl[2 * jp + 1][0] = r[2]; bl[2 * jp + 1][1] = r[3];
            }
            #pragma unroll
            for (int i = 0; i < 4; i++)
                #pragma unroll
                for (int j = 0; j < 4; j++) mma16(acc[i][j], ah[i], bl[j]);
            #pragma unroll
            for (int i = 0; i < 4; i++)
                #pragma unroll
                for (int j = 0; j < 4; j++) mma16(acc[i][j], al[i], bh[j]);
            #pragma unroll
            for (int i = 0; i < 4; i++)
                #pragma unroll
                for (int j = 0; j < 4; j++) mma16(acc[i][j], ah[i], bh[j]);
        }
    };

    const int NS = ksteps;

    issue(ks0 * BK, 0); CPC();
    issue((ks0 + 1) * BK, 1); CPC();

    #pragma unroll 1
    for (int s = 0; s < NS; s++) {
        if (s < NS - 1) { CPW(1); } else { CPW(0); }
        __syncthreads();
        compute(s % 3);
        if (s + 2 < NS) { issue((ks0 + s + 2) * BK, (s + 2) % 3); CPC(); }
    }

    // epilogue
    if (MODE == 1) {
        #pragma unroll
        for (int i = 0; i < 4; i++) {
            int row = bm + wm + i * 16 + g;
            #pragma unroll
            for (int j = 0; j < 4; j++) {
                int col = bn + wn + j * 8 + 2 * t;
                float* p0 = Cf + (size_t)row * 1024 + col;
                float* p1 = Cf + (size_t)(row + 8) * 1024 + col;
                REDADD(p0,     acc[i][j][0]);
                REDADD(p0 + 1, acc[i][j][1]);
                REDADD(p1,     acc[i][j][2]);
                REDADD(p1 + 1, acc[i][j][3]);
            }
        }
    } else if (MODE == 3) {
        bf16* Chz = Ch + (size_t)z * cZ;
        bf16* Clz = Cl + (size_t)z * cZ;
        #pragma unroll
        for (int i = 0; i < 4; i++) {
            int row = bm + wm + i * 16 + g;
            #pragma unroll
            for (int j = 0; j < 4; j++) {
                int col = bn + wn + j * 8 + 2 * t;
                #pragma unroll
                for (int e = 0; e < 2; e++) {
                    float v0 = acc[i][j][2 * e], v1 = acc[i][j][2 * e + 1];
                    bf16 h0 = __float2bfloat16_rn(v0);
                    bf16 h1 = __float2bfloat16_rn(v1);
                    bf16 l0 = __float2bfloat16_rn(v0 - __bfloat162float(h0));
                    bf16 l1 = __float2bfloat16_rn(v1 - __bfloat162float(h1));
                    size_t o = (size_t)(row + 8 * e) * 1024 + col;
                    __nv_bfloat162 hv; hv.x = h0; hv.y = h1;
                    __nv_bfloat162 lv; lv.x = l0; lv.y = l1;
                    *(__nv_bfloat162*)(Chz + o) = hv;
                    *(__nv_bfloat162*)(Clz + o) = lv;
                }
            }
        }
    } else {
        #pragma unroll
        for (int i = 0; i < 4; i++) {
            int row = bm + wm + i * 16 + g;
            #pragma unroll
            for (int j = 0; j < 4; j++) {
                int col = bn + wn + j * 8 + 2 * t;
                *(float2*)(Cf + (size_t)row * 1024 + col) =
                    make_float2(acc[i][j][0], acc[i][j][1]);
                *(float2*)(Cf + (size_t)(row + 8) * 1024 + col) =
                    make_float2(acc[i][j][2], acc[i][j][3]);
            }
        }
    }
}

// ---------------- SYRK: S_b = X_b^T X_b (upper-tri tiles + mirror) --------------
#define SPL 8192

__global__ __launch_bounds__(256, 2)
void syrk_mma(const bf16* __restrict__ gXh, const bf16* __restrict__ gXl,
              float* __restrict__ Sf)
{
    extern __shared__ __align__(16) char smc[];
    const int z = blockIdx.z;
    const int tri = blockIdx.x % 36;
    const int ksl = blockIdx.x / 36;
    int ib = 0, rem = tri;
    while (rem >= 8 - ib) { rem -= 8 - ib; ib++; }
    const int jb = ib + rem;

    const bf16* Xh = gXh + (size_t)z * Nt * Dd;
    const bf16* Xl = gXl + (size_t)z * Nt * Dd;
    float* Sfz = Sf + (size_t)z * Dd * Dd;

    const int tid = threadIdx.x;
    const int wid = tid >> 5, lid = tid & 31;
    const int g = lid >> 2, t = lid & 3;
    const int wm = (wid >> 2) * 64;
    const int wn = (wid & 3) * 32;
    const uint32_t sbase = smem_u32(smc);

    const uint32_t lrow = (uint32_t)tid >> 3;
    const uint32_t lc0 = ((uint32_t)tid & 7) * 2;
    const uint32_t d0 = swz256(lrow, lc0);
    const uint32_t d1 = swz256(lrow, lc0 + 1);
    const int tok0 = ksl * (Nt / 4);
    const bf16* pAh = Xh + (size_t)(tok0 + lrow) * 1024 + ib * 128 + lc0 * 8;
    const bf16* pAl = Xl + (size_t)(tok0 + lrow) * 1024 + ib * 128 + lc0 * 8;
    const bf16* pBh = Xh + (size_t)(tok0 + lrow) * 1024 + jb * 128 + lc0 * 8;
    const bf16* pBl = Xl + (size_t)(tok0 + lrow) * 1024 + jb * 128 + lc0 * 8;

    auto issue = [&](int kc, int st) {
        uint32_t sb2 = sbase + (uint32_t)st * STAGE_B;
        size_t adv = (size_t)kc * 32 * 1024;
        CPA(sb2 + d0,           pAh + adv);
        CPA(sb2 + d1,           pAh + adv + 8);
        CPA(sb2 + SPL + d0,     pAl + adv);
        CPA(sb2 + SPL + d1,     pAl + adv + 8);
        CPA(sb2 + 2 * SPL + d0, pBh + adv);
        CPA(sb2 + 2 * SPL + d1, pBh + adv + 8);
        CPA(sb2 + 3 * SPL + d0, pBl + adv);
        CPA(sb2 + 3 * SPL + d1, pBl + adv + 8);
    };

    float acc[4][4][4];
    #pragma unroll
    for (int i = 0; i < 4; i++)
        #pragma unroll
        for (int j = 0; j < 4; j++)
            #pragma unroll
            for (int e = 0; e < 4; e++) acc[i][j][e] = 0.0f;

    const uint32_t akrow = (uint32_t)((lid & 7) + ((lid >> 4) << 3));
    const uint32_t amch  = (uint32_t)((lid >> 3) & 1);
    const uint32_t bkrow = (uint32_t)((lid & 7) + (((lid >> 3) & 1) << 3));
    const uint32_t bnch  = (uint32_t)(lid >> 4);

    auto compute = [&](int buf) {
        const uint32_t bb = sbase + (uint32_t)buf * STAGE_B;
        #pragma unroll
        for (int ks2 = 0; ks2 < 2; ks2++) {
            uint32_t ah[4][4], al[4][4], bh[4][2], bl[4][2];
            #pragma unroll
            for (int i = 0; i < 4; i++) {
                uint32_t off = swz256((uint32_t)(ks2 * 16) + akrow,
                                      (uint32_t)(wm >> 3) + 2u * i + amch);
                LDM4T(ah[i], bb + off);
                LDM4T(al[i], bb + SPL + off);
            }
            #pragma unroll
            for (int jp = 0; jp < 2; jp++) {
                uint32_t off = swz256((uint32_t)(ks2 * 16) + bkrow,
                                      (uint32_t)(wn >> 3) + 2u * jp + bnch);
                uint32_t r[4];
                LDM4T(r, bb + 2 * SPL + off);
                bh[2 * jp][0] = r[0]; bh[2 * jp][1] = r[1];
                bh[2 * jp + 1][0] = r[2]; bh[2 * jp + 1][1] = r[3];
                LDM4T(r, bb + 3 * SPL + off);
                bl[2 * jp][0] = r[0]; bl[2 * jp][1] = r[1];
                bl[2 * jp + 1][0] = r[2]; bl[2 * jp + 1][1] = r[3];
            }
            #pragma unroll
            for (int i = 0; i < 4; i++)
                #pragma unroll
                for (int j = 0; j < 4; j++) mma16(acc[i][j], ah[i], bl[j]);
            #pragma unroll
            for (int i = 0; i < 4; i++)
                #pragma unroll
                for (int j = 0; j < 4; j++) mma16(acc[i][j], al[i], bh[j]);
            #pragma unroll
            for (int i = 0; i < 4; i++)
                #pragma unroll
                for (int j = 0; j < 4; j++) mma16(acc[i][j], ah[i], bh[j]);
        }
    };

    const int NS = (Nt / 4) / 32;

    issue(0, 0); CPC();
    issue(1, 1); CPC();

    #pragma unroll 1
    for (int s = 0; s < NS; s++) {
        if (s < NS - 1) { CPW(1); } else { CPW(0); }
        __syncthreads();
        compute(s % 3);
        if (s + 2 < NS) { issue(s + 2, (s + 2) % 3); CPC(); }
    }

    #pragma unroll
    for (int i = 0; i < 4; i++) {
        #pragma unroll
        for (int j = 0; j < 4; j++) {
            #pragma unroll
            for (int e = 0; e < 2; e++) {
                int r = ib * 128 + wm + i * 16 + 8 * e + g;
                int c = jb * 128 + wn + j * 8 + 2 * t;
                float v0 = acc[i][j][2 * e], v1 = acc[i][j][2 * e + 1];
                REDADD(Sfz + (size_t)r * 1024 + c,     v0);
                REDADD(Sfz + (size_t)r * 1024 + c + 1, v1);
                if (ib != jb) {
                    REDADD(Sfz + (size_t)c * 1024 + r,       v0);
                    REDADD(Sfz + (size_t)(c + 1) * 1024 + r, v1);
                }
            }
        }
    }
}

// ---------------- G_bh = P_h @ WT_h^T (64x64x1024, split-K=4) -------------------
#define GPLB 16384
#define GSMB (4 * GPLB)
__global__ __launch_bounds__(128)
void g_mma(const bf16* __restrict__ Ph, const bf16* __restrict__ Pl,
           const bf16* __restrict__ WTh, const bf16* __restrict__ WTl,
           float* __restrict__ G)
{
    extern __shared__ __align__(16) char smg[];
    const int ksl = blockIdx.x;
    const int bh = blockIdx.y;
    const int b = bh >> 4, h = bh & 15;
    const size_t abase = (size_t)b * Dd * Dd + (size_t)(h * DH) * 1024 + ksl * 256;
    const size_t bbase = (size_t)(h * DH) * 1024 + ksl * 256;

    const int tid = threadIdx.x;
    const int wid = tid >> 5, lid = tid & 31;
    const int g = lid >> 2, t = lid & 3;
    const int wm = (wid >> 1) * 32, wn = (wid & 1) * 32;
    const uint32_t sb = smem_u32(smg);

    const uint32_t lrow = (uint32_t)tid >> 1;
    const uint32_t lc0 = ((uint32_t)tid & 1) * 8;

    float acc[2][4][4];
    #pragma unroll
    for (int i = 0; i < 2; i++)
        #pragma unroll
        for (int j = 0; j < 4; j++)
            #pragma unroll
            for (int e = 0; e < 4; e++) acc[i][j][e] = 0.0f;

    uint32_t arow[2], brw[2];
    #pragma unroll
    for (int i = 0; i < 2; i++) arow[i] = (uint32_t)(wm + i * 16 + (lid & 15));
    #pragma unroll
    for (int jp = 0; jp < 2; jp++)
        brw[jp] = (uint32_t)(wn + jp * 16 + (lid & 7) + ((lid >> 4) << 3));
    const uint32_t aco = (uint32_t)(lid >> 4);
    const uint32_t bco = (uint32_t)((lid >> 3) & 1);

    #pragma unroll 1
    for (int kc = 0; kc < 2; kc++) {
        const bf16* a_h = Ph + abase + (size_t)lrow * 1024 + kc * 128;
        const bf16* a_l = Pl + abase + (size_t)lrow * 1024 + kc * 128;
        const bf16* b_h = WTh + bbase + (size_t)lrow * 1024 + kc * 128;
        const bf16* b_l = WTl + bbase + (size_t)lrow * 1024 + kc * 128;
        #pragma unroll
        for (int cc = 0; cc < 8; cc++) {
            uint32_t c = lc0 + cc;
            uint32_t d = swz256(lrow, c);
            CPA(sb + d,            a_h + c * 8);
            CPA(sb + GPLB + d,     a_l + c * 8);
            CPA(sb + 2 * GPLB + d, b_h + c * 8);
            CPA(sb + 3 * GPLB + d, b_l + c * 8);
        }
        CPC(); CPW(0);
        __syncthreads();
        #pragma unroll
        for (int ks = 0; ks < 8; ks++) {
            uint32_t ah[2][4], al2[2][4], bh2[4][2], bl2[4][2];
            #pragma unroll
            for (int i = 0; i < 2; i++) {
                uint32_t off = swz256(arow[i], (uint32_t)(ks * 2) + aco);
                LDM4(ah[i], sb + off);
                LDM4(al2[i], sb + GPLB + off);
            }
            #pragma unroll
            for (int jp = 0; jp < 2; jp++) {
                uint32_t off = swz256(brw[jp], (uint32_t)(ks * 2) + bco);
                uint32_t rr[4];
                LDM4(rr, sb + 2 * GPLB + off);
                bh2[2 * jp][0] = rr[0]; bh2[2 * jp][1] = rr[1];
                bh2[2 * jp + 1][0] = rr[2]; bh2[2 * jp + 1][1] = rr[3];
                LDM4(rr, sb + 3 * GPLB + off);
                bl2[2 * jp][0] = rr[0]; bl2[2 * jp][1] = rr[1];
                bl2[2 * jp + 1][0] = rr[2]; bl2[2 * jp + 1][1] = rr[3];
            }
            #pragma unroll
            for (int i = 0; i < 2; i++)
                #pragma unroll
                for (int j = 0; j < 4; j++) mma16(acc[i][j], ah[i], bl2[j]);
            #pragma unroll
            for (int i = 0; i < 2; i++)
                #pragma unroll
                for (int j = 0; j < 4; j++) mma16(acc[i][j], al2[i], bh2[j]);
            #pragma unroll
            for (int i = 0; i < 2; i++)
                #pragma unroll
                for (int j = 0; j < 4; j++) mma16(acc[i][j], ah[i], bh2[j]);
        }
        __syncthreads();
    }

    float* gp = G + (size_t)bh * (DH * DH);
    #pragma unroll
    for (int i = 0; i < 2; i++) {
        #pragma unroll
        for (int j = 0; j < 4; j++) {
            int c = wm + i * 16 + g;
            int d = wn + j * 8 + 2 * t;
            REDADD(gp + c * DH + d,           acc[i][j][0]);
            REDADD(gp + c * DH + d + 1,       acc[i][j][1]);
            REDADD(gp + (c + 8) * DH + d,     acc[i][j][2]);
            REDADD(gp + (c + 8) * DH + d + 1, acc[i][j][3]);
        }
    }
}

// ---------------- split fp32 -> bf16 hi/lo planes ------------------------------
__global__ __launch_bounds__(256)
void split_f32(const float* __restrict__ src, bf16* __restrict__ h, bf16* __restrict__ l)
{
    size_t i = ((size_t)blockIdx.x * 256 + threadIdx.x) * 4;
    float4 v = *(const float4*)(src + i);
    bf16 h0 = __float2bfloat16_rn(v.x), h1 = __float2bfloat16_rn(v.y);
    bf16 h2 = __float2bfloat16_rn(v.z), h3 = __float2bfloat16_rn(v.w);
    bf16 l0 = __float2bfloat16_rn(v.x - __bfloat162float(h0));
    bf16 l1 = __float2bfloat16_rn(v.y - __bfloat162float(h1));
    bf16 l2 = __float2bfloat16_rn(v.z - __bfloat162float(h2));
    bf16 l3 = __float2bfloat16_rn(v.w - __bfloat162float(h3));
    __nv_bfloat162 a, b;
    a.x = h0; a.y = h1; b.x = h2; b.y = h3;
    *(__nv_bfloat162*)(h + i) = a; *(__nv_bfloat162*)(h + i + 2) = b;
    a.x = l0; a.y = l1; b.x = l2; b.y = l3;
    *(__nv_bfloat162*)(l + i) = a; *(__nv_bfloat162*)(l + i + 2) = b;
}

// ---------------- weight prep: z=0 transpose+split Wqk; z=1 split Wv -------------
__global__ __launch_bounds__(256)
void prep_w(const float* __restrict__ Wqk, const float* __restrict__ Wv,
            bf16* __restrict__ WTh, bf16* __restrict__ WTl,
            bf16* __restrict__ WVh, bf16* __restrict__ WVl)
{
    __shared__ float tbuf[32][33];
    int bx = blockIdx.x * 32, by = blockIdx.y * 32;
    int tx = threadIdx.x & 31, ty = threadIdx.x >> 5;
    if (blockIdx.z == 0) {
        #pragma unroll
        for (int i = 0; i < 4; i++) {
            int r = ty + i * 8;
            tbuf[r][tx] = Wqk[(size_t)(by + r) * Dd + bx + tx];
        }
        __syncthreads();
        #pragma unroll
        for (int i = 0; i < 4; i++) {
            int r = ty + i * 8;
            float v = tbuf[tx][r];
            bf16 h = __float2bfloat16_rn(v);
            bf16 l = __float2bfloat16_rn(v - __bfloat162float(h));
            size_t o = (size_t)(bx + r) * Dd + by + tx;
            WTh[o] = h; WTl[o] = l;
        }
    } else {
        #pragma unroll
        for (int i = 0; i < 4; i++) {
            int r = by + ty + i * 8;
            size_t o = (size_t)r * Dd + bx + tx;
            float v = Wv[o];
            bf16 h = __float2bfloat16_rn(v);
            bf16 l = __float2bfloat16_rn(v - __bfloat162float(h));
            WVh[o] = h; WVl[o] = l;
        }
    }
}

// ---------------- build_mT with fused softmax -----------------------------------
// Gr -> softmax per row -> MT_b[j, h*64+d] = sum_c attn[c,d]*Wout[h*64+c, j]
__global__ __launch_bounds__(256)
void build_mT(const float* __restrict__ Gr, const float* __restrict__ tau,
              const float* __restrict__ Wout,
              bf16* __restrict__ MTh, bf16* __restrict__ MTl)
{
    const int bh = blockIdx.y;
    const int b = bh >> 4, h = bh & 15;
    const int j0 = blockIdx.x * 64;

    __shared__ float Asm[DH * DH];
    __shared__ float Ws[DH][64];
    __shared__ float diag[DH];

    const int tid = threadIdx.x;
    const float* gp = Gr + (size_t)bh * (DH * DH);
    for (int e = tid; e < DH * DH; e += 256) Asm[e] = gp[e];

    #pragma unroll
    for (int i = 0; i < 4; i++) {
        int idx = tid + i * 256;
        int r = idx >> 4;
        int c4 = (idx & 15) * 4;
        *(float4*)&Ws[r][c4] =
            *(const float4*)(Wout + (size_t)(h * DH + r) * Dd + j0 + c4);
    }
    __syncthreads();
    if (tid < DH) diag[tid] = Asm[tid * DH + tid];
    __syncthreads();

    // in-place row softmax (thread c owns row c)
    if (tid < DH) {
        const int c = tid;
        const float tauh = tau[h];
        const float scale = 0.011048543456039806f;   // 1/sqrt(8192)
        const float qc = diag[c];
        float l[DH];
        float mx = -1e30f;
        #pragma unroll 8
        for (int d = 0; d < DH; d++) {
            float v = (2.0f * Asm[c * DH + d] - qc - diag[d]) * scale * tauh;
            l[d] = v;
            mx = fmaxf(mx, v);
        }
        float sum = 0.0f;
        #pragma unroll 8
        for (int d = 0; d < DH; d++) { float e = __expf(l[d] - mx); l[d] = e; sum += e; }
        const float inv = 1.0f / sum;
        #pragma unroll 8
        for (int d = 0; d < DH; d++) Asm[c * DH + d] = l[d] * inv;
    }
    __syncthreads();

    const int tx = tid & 15, ty = tid >> 4;
    float acc[4][4];
    #pragma unroll
    for (int i = 0; i < 4; i++)
        #pragma unroll
        for (int e = 0; e < 4; e++) acc[i][e] = 0.0f;

    for (int c = 0; c < DH; c++) {
        float4 av = *(float4*)&Asm[c * DH + tx * 4];
        #pragma unroll
        for (int i = 0; i < 4; i++) {
            float w = Ws[c][ty * 4 + i];
            acc[i][0] += w * av.x;
            acc[i][1] += w * av.y;
            acc[i][2] += w * av.z;
            acc[i][3] += w * av.w;
        }
    }

    bf16* Mh = MTh + (size_t)b * Dd * Dd;
    bf16* Ml = MTl + (size_t)b * Dd * Dd;
    #pragma unroll
    for (int i = 0; i < 4; i++) {
        int j = j0 + ty * 4 + i;
        size_t o = (size_t)j * Dd + h * DH + tx * 4;
        #pragma unroll
        for (int e = 0; e < 4; e++) {
            float v = acc[i][e];
            bf16 hh = __float2bfloat16_rn(v);
            bf16 ll = __float2bfloat16_rn(v - __bfloat162float(hh));
            Mh[o + e] = hh; Ml[o + e] = ll;
        }
    }
}

// ----------------------------------------------------------------------------------
extern "C" void kernel_launch(void* const* d_in, const int* in_sizes, int n_in,
                              void* d_out, int out_size)
{
    const float* x    = (const float*)d_in[0];
    const float* Wqk  = (const float*)d_in[1];
    const float* Wv   = (const float*)d_in[2];
    const float* Wout = (const float*)d_in[3];
    const float* tau  = (const float*)d_in[4];
    float* out = (float*)d_out;

    void *pxh, *pxl, *pwth, *pwtl, *pwvh, *pwvl, *pacc, *psh, *psl, *pph, *ppl,
         *pmth, *pmtl, *pnth, *pntl;
    cudaGetSymbolAddress(&pxh, g_xh);
    cudaGetSymbolAddress(&pxl, g_xl);
    cudaGetSymbolAddress(&pwth, g_wth);
    cudaGetSymbolAddress(&pwtl, g_wtl);
    cudaGetSymbolAddress(&pwvh, g_wvh);
    cudaGetSymbolAddress(&pwvl, g_wvl);
    cudaGetSymbolAddress(&pacc, g_acc);
    cudaGetSymbolAddress(&psh, g_sh);
    cudaGetSymbolAddress(&psl, g_sl);
    cudaGetSymbolAddress(&pph, g_ph);
    cudaGetSymbolAddress(&ppl, g_pl);
    cudaGetSymbolAddress(&pmth, g_mth);
    cudaGetSymbolAddress(&pmtl, g_mtl);
    cudaGetSymbolAddress(&pnth, g_nth);
    cudaGetSymbolAddress(&pntl, g_ntl);

    bf16 *Xh = (bf16*)pxh, *Xl = (bf16*)pxl;
    bf16 *WTh = (bf16*)pwth, *WTl = (bf16*)pwtl;
    bf16 *WVh = (bf16*)pwvh, *WVl = (bf16*)pwvl;
    float* Acc = (float*)pacc;
    float* Sf  = Acc + SF_OFF;
    float* NTf = Acc + NTF_OFF;
    float* Gr  = Acc + GR_OFF;
    bf16 *Sh = (bf16*)psh, *Sl = (bf16*)psl;
    bf16 *Ph = (bf16*)pph, *Pl = (bf16*)ppl;
    bf16 *MTh = (bf16*)pmth, *MTl = (bf16*)pmtl;
    bf16 *NTh = (bf16*)pnth, *NTl = (bf16*)pntl;

    cudaFuncSetAttribute(mma_gemm<1>, cudaFuncAttributeMaxDynamicSharedMemorySize, SMB);
    cudaFuncSetAttribute(mma_gemm<3>, cudaFuncAttributeMaxDynamicSharedMemorySize, SMB);
    cudaFuncSetAttribute(syrk_mma,    cudaFuncAttributeMaxDynamicSharedMemorySize, SMB);
    cudaFuncSetAttribute(g_mma,       cudaFuncAttributeMaxDynamicSharedMemorySize, GSMB);

    // 0: one memset for all fp32 accumulators + out (split-K targets), splits, prep
    cudaMemsetAsync(Acc, 0, ACC_TOT * sizeof(float));
    cudaMemsetAsync(out, 0, (size_t)Mrows * Dd * sizeof(float));
    split_f32<<<(size_t)Mrows * Dd / 1024, 256>>>(x, Xh, Xl);
    prep_w<<<dim3(32, 32, 2), 256>>>(Wqk, Wv, WTh, WTl, WVh, WVl);
    // 1: S_b = X_b^T X_b (upper-tri + mirror, token split-K=4)
    syrk_mma<<<dim3(144, 1, 2), 256, SMB>>>(Xh, Xl, Sf);
    // 2: split S
    split_f32<<<(size_t)Bq * Dd * Dd / 1024, 256>>>(Sf, Sh, Sl);
    // 3: P_b = WT @ S_b
    mma_gemm<3><<<dim3(8, 8, 2), 256, SMB>>>(WTh, WTl, 0, Sh, Sl, (size_t)Dd * Dd,
                                             nullptr, nullptr, Ph, Pl, (size_t)Dd * Dd,
                                             8, 32);
    // 4: G_bh = P_h @ WT_h^T
    g_mma<<<dim3(4, 32), 128, GSMB>>>(Ph, Pl, WTh, WTl, Gr);
    // 5: softmax + fold attn into W_out (fused)
    build_mT<<<dim3(16, 32), 256>>>(Gr, tau, Wout, MTh, MTl);
    // 6: NT_b = MT_b @ Wv^T  (split-K=4)
    mma_gemm<1><<<dim3(32, 8, 2), 256, SMB>>>(MTh, MTl, (size_t)Dd * Dd,
                                              WVh, WVl, 0,
                                              NTf, NTf + (size_t)Dd * Dd,
                                              nullptr, nullptr, 0, 8, 8);
    // 7: split NT
    split_f32<<<(size_t)Bq * Dd * Dd / 1024, 256>>>(NTf, NTh, NTl);
    // 8: out_b = X_b @ N_b  (split-K=2, REDADD)
    mma_gemm<1><<<dim3(16, 64, 2), 256, SMB>>>(Xh, Xl, (size_t)Nt * Dd,
                                               NTh, NTl, (size_t)Dd * Dd,
                                               out, out + (size_t)Nt * Dd,
                                               nullptr, nullptr, 0, 8, 16);
}

// round 17
// speedup vs baseline: 1.0619x; 1.0619x over previous
#include <cuda_runtime.h>
#include <cuda_bf16.h>
#include <cstdint>
#include <cstddef>

typedef __nv_bfloat16 bf16;

// Problem constants
#define Bq   2
#define Nt   8192
#define Dd   1024
#define Hh   16
#define DH   64
#define Mrows (Bq * Nt)

// ---------------- scratch ---------------------------------------------------
__device__ bf16  g_xh[(size_t)Mrows * Dd];
__device__ bf16  g_xl[(size_t)Mrows * Dd];
__device__ bf16  g_wth[(size_t)Dd * Dd];
__device__ bf16  g_wtl[(size_t)Dd * Dd];
__device__ bf16  g_wvh[(size_t)Dd * Dd];
__device__ bf16  g_wvl[(size_t)Dd * Dd];
// fp32 atomic arena: Sf | NTf | Gr
#define SF_OFF  0
#define NTF_OFF ((size_t)Bq * Dd * Dd)
#define GR_OFF  (2 * (size_t)Bq * Dd * Dd)
#define ACC_TOT (2 * (size_t)Bq * Dd * Dd + (size_t)Bq * Hh * DH * DH)
__device__ float g_acc[ACC_TOT];
__device__ bf16  g_sh [(size_t)Bq * Dd * Dd];
__device__ bf16  g_sl [(size_t)Bq * Dd * Dd];
__device__ bf16  g_ph [(size_t)Bq * Dd * Dd];
__device__ bf16  g_pl [(size_t)Bq * Dd * Dd];
__device__ bf16  g_mth[(size_t)Bq * Dd * Dd];
__device__ bf16  g_mtl[(size_t)Bq * Dd * Dd];
__device__ bf16  g_nth[(size_t)Bq * Dd * Dd];
__device__ bf16  g_ntl[(size_t)Bq * Dd * Dd];

// ---------------- PTX helpers -------------------------------------------------
__device__ __forceinline__ uint32_t smem_u32(const void* p) {
    uint32_t a;
    asm("{ .reg .u64 t; cvta.to.shared.u64 t, %1; cvt.u32.u64 %0, t; }"
        : "=r"(a) : "l"(p));
    return a;
}

#define LDM4(r, addr)                                                          \
    asm volatile("ldmatrix.sync.aligned.m8n8.x4.shared.b16 {%0,%1,%2,%3}, [%4];" \
        : "=r"((r)[0]), "=r"((r)[1]), "=r"((r)[2]), "=r"((r)[3]) : "r"(addr))

#define LDM4T(r, addr)                                                         \
    asm volatile("ldmatrix.sync.aligned.m8n8.x4.trans.shared.b16 {%0,%1,%2,%3}, [%4];" \
        : "=r"((r)[0]), "=r"((r)[1]), "=r"((r)[2]), "=r"((r)[3]) : "r"(addr))

__device__ __forceinline__ void mma16(float* c, const uint32_t* a, const uint32_t* b) {
    asm volatile(
        "mma.sync.aligned.m16n8k16.row.col.f32.bf16.bf16.f32 "
        "{%0,%1,%2,%3}, {%4,%5,%6,%7}, {%8,%9}, {%0,%1,%2,%3};"
        : "+f"(c[0]), "+f"(c[1]), "+f"(c[2]), "+f"(c[3])
        : "r"(a[0]), "r"(a[1]), "r"(a[2]), "r"(a[3]), "r"(b[0]), "r"(b[1]));
}

#define CPA(dst, src) \
    asm volatile("cp.async.cg.shared.global [%0], [%1], 16;" :: "r"(dst), "l"(src) : "memory")
#define CPC() asm volatile("cp.async.commit_group;" ::: "memory")
#define CPW(n) asm volatile("cp.async.wait_group %0;" :: "n"(n) : "memory")

#define REDADD(ptr, v) \
    asm volatile("red.global.add.f32 [%0], %1;" :: "l"(ptr), "f"(v) : "memory")

__device__ __forceinline__ uint32_t swz(uint32_t row, uint32_t c) {
    return row * 64u + (((c ^ ((row >> 1) & 3u)) & 3u) << 4);
}
__device__ __forceinline__ uint32_t swz256(uint32_t row, uint32_t c) {
    return row * 256u + (((c ^ (row & 15u)) & 15u) << 4);
}

// ---------------- bf16 split GEMM, 128x128 tile, 256 threads, 2 CTAs/SM --------
// MODE 0: fp32 store; MODE 1: fp32 red.add; MODE 3: split-bf16 store (ld 1024).
#define BK 32
#define PLANE_B 8192
#define STAGE_B (4 * PLANE_B)
#define NSTAGE  3
#define SMB     (NSTAGE * STAGE_B)    // 98304
#define OFF_AL  PLANE_B
#define OFF_BH  (2 * PLANE_B)
#define OFF_BL  (3 * PLANE_B)

template <int MODE>
__global__ __launch_bounds__(256, 2)
void mma_gemm(const bf16* __restrict__ gAh, const bf16* __restrict__ gAl, size_t aZ,
              const bf16* __restrict__ gBh, const bf16* __restrict__ gBl, size_t bZ,
              float* Cf0, float* Cf1, bf16* Ch, bf16* Cl, size_t cZ,
              int nxt, int ksteps)
{
    extern __shared__ __align__(16) char smc[];
    const int z = blockIdx.z;
    const int ks0 = (blockIdx.x / nxt) * ksteps;
    const int bn  = (blockIdx.x % nxt) * 128;
    const bf16* Ah = gAh + (size_t)z * aZ;
    const bf16* Al = gAl + (size_t)z * aZ;
    const bf16* Bh = gBh + (size_t)z * bZ;
    const bf16* Bl = gBl + (size_t)z * bZ;
    float* Cf = z ? Cf1 : Cf0;

    const int bm = blockIdx.y * 128;
    const int tid = threadIdx.x;
    const int wid = tid >> 5;
    const int lid = tid & 31;
    const int g = lid >> 2;
    const int t = lid & 3;
    const int wm = (wid >> 2) * 64;
    const int wn = (wid & 3) * 32;

    const uint32_t sbase = smem_u32(smc);

    const uint32_t rA = (uint32_t)tid >> 2;
    const uint32_t cC = (uint32_t)tid & 3;
    const uint32_t rA1 = rA + 64;
    const uint32_t sw0 = swz(rA, cC);
    const uint32_t sw1 = swz(rA1, cC);
    const bf16* gah0 = Ah + (size_t)(bm + rA) * 1024 + cC * 8;
    const bf16* gah1 = Ah + (size_t)(bm + rA1) * 1024 + cC * 8;
    const bf16* gal0 = Al + (size_t)(bm + rA) * 1024 + cC * 8;
    const bf16* gal1 = Al + (size_t)(bm + rA1) * 1024 + cC * 8;
    const bf16* gbh0 = Bh + (size_t)(bn + rA) * 1024 + cC * 8;
    const bf16* gbh1 = Bh + (size_t)(bn + rA1) * 1024 + cC * 8;
    const bf16* gbl0 = Bl + (size_t)(bn + rA) * 1024 + cC * 8;
    const bf16* gbl1 = Bl + (size_t)(bn + rA1) * 1024 + cC * 8;

    auto issue = [&](int k0, int st) {
        uint32_t sb2 = sbase + (uint32_t)st * STAGE_B;
        CPA(sb2 + sw0,          gah0 + k0);
        CPA(sb2 + sw1,          gah1 + k0);
        CPA(sb2 + OFF_AL + sw0, gal0 + k0);
        CPA(sb2 + OFF_AL + sw1, gal1 + k0);
        CPA(sb2 + OFF_BH + sw0, gbh0 + k0);
        CPA(sb2 + OFF_BH + sw1, gbh1 + k0);
        CPA(sb2 + OFF_BL + sw0, gbl0 + k0);
        CPA(sb2 + OFF_BL + sw1, gbl1 + k0);
    };

    float acc[4][4][4];
    #pragma unroll
    for (int i = 0; i < 4; i++)
        #pragma unroll
        for (int j = 0; j < 4; j++)
            #pragma unroll
            for (int e = 0; e < 4; e++) acc[i][j][e] = 0.0f;

    uint32_t arow[4], brow[2];
    #pragma unroll
    for (int i = 0; i < 4; i++) arow[i] = (uint32_t)(wm + i * 16 + (lid & 15));
    #pragma unroll
    for (int jp = 0; jp < 2; jp++)
        brow[jp] = (uint32_t)(wn + jp * 16 + (lid & 7) + ((lid >> 4) << 3));
    const uint32_t aco = (uint32_t)(lid >> 4);
    const uint32_t bco = (uint32_t)((lid >> 3) & 1);

    auto compute = [&](int buf) {
        const uint32_t bb = sbase + (uint32_t)buf * STAGE_B;
        #pragma unroll
        for (int ks2 = 0; ks2 < 2; ks2++) {
            uint32_t ah[4][4], al[4][4], bh[4][2], bl[4][2];
            #pragma unroll
            for (int i = 0; i < 4; i++) {
                uint32_t off = swz(arow[i], ks2 * 2 + aco);
                LDM4(ah[i], bb + off);
                LDM4(al[i], bb + OFF_AL + off);
            }
            #pragma unroll
            for (int jp = 0; jp < 2; jp++) {
                uint32_t off = swz(brow[jp], ks2 * 2 + bco);
                uint32_t r[4];
                LDM4(r, bb + OFF_BH + off);
                bh[2 * jp][0] = r[0]; bh[2 * jp][1] = r[1];
                bh[2 * jp + 1][0] = r[2]; bh[2 * jp + 1][1] = r[3];
                LDM4(r, bb + OFF_BL + off);
                bl[2 * jp][0] = r[0]; bl[2 * jp][1] = r[1];
                bl[2 * jp + 1][0] = r[2]; bl[2 * jp + 1][1] = r[3];
            }
            #pragma unroll
            for (int i = 0; i < 4; i++)
                #pragma unroll
                for (int j = 0; j < 4; j++) mma16(acc[i][j], ah[i], bl[j]);
            #pragma unroll
            for (int i = 0; i < 4; i++)
                #pragma unroll
                for (int j = 0; j < 4; j++) mma16(acc[i][j], al[i], bh[j]);
            #pragma unroll
            for (int i = 0; i < 4; i++)
                #pragma unroll
                for (int j = 0; j < 4; j++) mma16(acc[i][j], ah[i], bh[j]);
        }
    };

    const int NS = ksteps;

    issue(ks0 * BK, 0); CPC();
    issue((ks0 + 1) * BK, 1); CPC();

    #pragma unroll 1
    for (int s = 0; s < NS; s++) {
        if (s < NS - 1) { CPW(1); } else { CPW(0); }
        __syncthreads();
        compute(s % 3);
        if (s + 2 < NS) { issue((ks0 + s + 2) * BK, (s + 2) % 3); CPC(); }
    }

    // epilogue
    if (MODE == 1) {
        #pragma unroll
        for (int i = 0; i < 4; i++) {
            int row = bm + wm + i * 16 + g;
            #pragma unroll
            for (int j = 0; j < 4; j++) {
                int col = bn + wn + j * 8 + 2 * t;
                float* p0 = Cf + (size_t)row * 1024 + col;
                float* p1 = Cf + (size_t)(row + 8) * 1024 + col;
                REDADD(p0,     acc[i][j][0]);
                REDADD(p0 + 1, acc[i][j][1]);
                REDADD(p1,     acc[i][j][2]);
                REDADD(p1 + 1, acc[i][j][3]);
            }
        }
    } else if (MODE == 3) {
        bf16* Chz = Ch + (size_t)z * cZ;
        bf16* Clz = Cl + (size_t)z * cZ;
        #pragma unroll
        for (int i = 0; i < 4; i++) {
            int row = bm + wm + i * 16 + g;
            #pragma unroll
            for (int j = 0; j < 4; j++) {
                int col = bn + wn + j * 8 + 2 * t;
                #pragma unroll
                for (int e = 0; e < 2; e++) {
                    float v0 = acc[i][j][2 * e], v1 = acc[i][j][2 * e + 1];
                    bf16 h0 = __float2bfloat16_rn(v0);
                    bf16 h1 = __float2bfloat16_rn(v1);
                    bf16 l0 = __float2bfloat16_rn(v0 - __bfloat162float(h0));
                    bf16 l1 = __float2bfloat16_rn(v1 - __bfloat162float(h1));
                    size_t o = (size_t)(row + 8 * e) * 1024 + col;
                    __nv_bfloat162 hv; hv.x = h0; hv.y = h1;
                    __nv_bfloat162 lv; lv.x = l0; lv.y = l1;
                    *(__nv_bfloat162*)(Chz + o) = hv;
                    *(__nv_bfloat162*)(Clz + o) = lv;
                }
            }
        }
    } else {
        #pragma unroll
        for (int i = 0; i < 4; i++) {
            int row = bm + wm + i * 16 + g;
            #pragma unroll
            for (int j = 0; j < 4; j++) {
                int col = bn + wn + j * 8 + 2 * t;
                *(float2*)(Cf + (size_t)row * 1024 + col) =
                    make_float2(acc[i][j][0], acc[i][j][1]);
                *(float2*)(Cf + (size_t)(row + 8) * 1024 + col) =
                    make_float2(acc[i][j][2], acc[i][j][3]);
            }
        }
    }
}

// ---------------- SYRK: S_b = X_b^T X_b (upper-tri tiles + mirror) --------------
#define SPL 8192

__global__ __launch_bounds__(256, 2)
void syrk_mma(const bf16* __restrict__ gXh, const bf16* __restrict__ gXl,
              float* __restrict__ Sf)
{
    extern __shared__ __align__(16) char smc[];
    const int z = blockIdx.z;
    const int tri = blockIdx.x % 36;
    const int ksl = blockIdx.x / 36;
    int ib = 0, rem = tri;
    while (rem >= 8 - ib) { rem -= 8 - ib; ib++; }
    const int jb = ib + rem;

    const bf16* Xh = gXh + (size_t)z * Nt * Dd;
    const bf16* Xl = gXl + (size_t)z * Nt * Dd;
    float* Sfz = Sf + (size_t)z * Dd * Dd;

    const int tid = threadIdx.x;
    const int wid = tid >> 5, lid = tid & 31;
    const int g = lid >> 2, t = lid & 3;
    const int wm = (wid >> 2) * 64;
    const int wn = (wid & 3) * 32;
    const uint32_t sbase = smem_u32(smc);

    const uint32_t lrow = (uint32_t)tid >> 3;
    const uint32_t lc0 = ((uint32_t)tid & 7) * 2;
    const uint32_t d0 = swz256(lrow, lc0);
    const uint32_t d1 = swz256(lrow, lc0 + 1);
    const int tok0 = ksl * (Nt / 4);
    const bf16* pAh = Xh + (size_t)(tok0 + lrow) * 1024 + ib * 128 + lc0 * 8;
    const bf16* pAl = Xl + (size_t)(tok0 + lrow) * 1024 + ib * 128 + lc0 * 8;
    const bf16* pBh = Xh + (size_t)(tok0 + lrow) * 1024 + jb * 128 + lc0 * 8;
    const bf16* pBl = Xl + (size_t)(tok0 + lrow) * 1024 + jb * 128 + lc0 * 8;

    auto issue = [&](int kc, int st) {
        uint32_t sb2 = sbase + (uint32_t)st * STAGE_B;
        size_t adv = (size_t)kc * 32 * 1024;
        CPA(sb2 + d0,           pAh + adv);
        CPA(sb2 + d1,           pAh + adv + 8);
        CPA(sb2 + SPL + d0,     pAl + adv);
        CPA(sb2 + SPL + d1,     pAl + adv + 8);
        CPA(sb2 + 2 * SPL + d0, pBh + adv);
        CPA(sb2 + 2 * SPL + d1, pBh + adv + 8);
        CPA(sb2 + 3 * SPL + d0, pBl + adv);
        CPA(sb2 + 3 * SPL + d1, pBl + adv + 8);
    };

    float acc[4][4][4];
    #pragma unroll
    for (int i = 0; i < 4; i++)
        #pragma unroll
        for (int j = 0; j < 4; j++)
            #pragma unroll
            for (int e = 0; e < 4; e++) acc[i][j][e] = 0.0f;

    const uint32_t akrow = (uint32_t)((lid & 7) + ((lid >> 4) << 3));
    const uint32_t amch  = (uint32_t)((lid >> 3) & 1);
    const uint32_t bkrow = (uint32_t)((lid & 7) + (((lid >> 3) & 1) << 3));
    const uint32_t bnch  = (uint32_t)(lid >> 4);

    auto compute = [&](int buf) {
        const uint32_t bb = sbase + (uint32_t)buf * STAGE_B;
        #pragma unroll
        for (int ks2 = 0; ks2 < 2; ks2++) {
            uint32_t ah[4][4], al[4][4], bh[4][2], bl[4][2];
            #pragma unroll
            for (int i = 0; i < 4; i++) {
                uint32_t off = swz256((uint32_t)(ks2 * 16) + akrow,
                                      (uint32_t)(wm >> 3) + 2u * i + amch);
                LDM4T(ah[i], bb + off);
                LDM4T(al[i], bb + SPL + off);
            }
            #pragma unroll
            for (int jp = 0; jp < 2; jp++) {
                uint32_t off = swz256((uint32_t)(ks2 * 16) + bkrow,
                                      (uint32_t)(wn >> 3) + 2u * jp + bnch);
                uint32_t r[4];
                LDM4T(r, bb + 2 * SPL + off);
                bh[2 * jp][0] = r[0]; bh[2 * jp][1] = r[1];
                bh[2 * jp + 1][0] = r[2]; bh[2 * jp + 1][1] = r[3];
                LDM4T(r, bb + 3 * SPL + off);
                bl[2 * jp][0] = r[0]; bl[2 * jp][1] = r[1];
                bl[2 * jp + 1][0] = r[2]; bl[2 * jp + 1][1] = r[3];
            }
            #pragma unroll
            for (int i = 0; i < 4; i++)
                #pragma unroll
                for (int j = 0; j < 4; j++) mma16(acc[i][j], ah[i], bl[j]);
            #pragma unroll
            for (int i = 0; i < 4; i++)
                #pragma unroll
                for (int j = 0; j < 4; j++) mma16(acc[i][j], al[i], bh[j]);
            #pragma unroll
            for (int i = 0; i < 4; i++)
                #pragma unroll
                for (int j = 0; j < 4; j++) mma16(acc[i][j], ah[i], bh[j]);
        }
    };

    const int NS = (Nt / 4) / 32;

    issue(0, 0); CPC();
    issue(1, 1); CPC();

    #pragma unroll 1
    for (int s = 0; s < NS; s++) {
        if (s < NS - 1) { CPW(1); } else { CPW(0); }
        __syncthreads();
        compute(s % 3);
        if (s + 2 < NS) { issue(s + 2, (s + 2) % 3); CPC(); }
    }

    #pragma unroll
    for (int i = 0; i < 4; i++) {
        #pragma unroll
        for (int j = 0; j < 4; j++) {
            #pragma unroll
            for (int e = 0; e < 2; e++) {
                int r = ib * 128 + wm + i * 16 + 8 * e + g;
                int c = jb * 128 + wn + j * 8 + 2 * t;
                float v0 = acc[i][j][2 * e], v1 = acc[i][j][2 * e + 1];
                REDADD(Sfz + (size_t)r * 1024 + c,     v0);
                REDADD(Sfz + (size_t)r * 1024 + c + 1, v1);
                if (ib != jb) {
                    REDADD(Sfz + (size_t)c * 1024 + r,       v0);
                    REDADD(Sfz + (size_t)(c + 1) * 1024 + r, v1);
                }
            }
        }
    }
}

// ---------------- G_bh = P_h @ WT_h^T (64x64x1024, split-K=4) -------------------
#define GPLB 16384
#define GSMB (4 * GPLB)
__global__ __launch_bounds__(128)
void g_mma(const bf16* __restrict__ Ph, const bf16* __restrict__ Pl,
           const bf16* __restrict__ WTh, const bf16* __restrict__ WTl,
           float* __restrict__ G)
{
    extern __shared__ __align__(16) char smg[];
    const int ksl = blockIdx.x;
    const int bh = blockIdx.y;
    const int b = bh >> 4, h = bh & 15;
    const size_t abase = (size_t)b * Dd * Dd + (size_t)(h * DH) * 1024 + ksl * 256;
    const size_t bbase = (size_t)(h * DH) * 1024 + ksl * 256;

    const int tid = threadIdx.x;
    const int wid = tid >> 5, lid = tid & 31;
    const int g = lid >> 2, t = lid & 3;
    const int wm = (wid >> 1) * 32, wn = (wid & 1) * 32;
    const uint32_t sb = smem_u32(smg);

    const uint32_t lrow = (uint32_t)tid >> 1;
    const uint32_t lc0 = ((uint32_t)tid & 1) * 8;

    float acc[2][4][4];
    #pragma unroll
    for (int i = 0; i < 2; i++)
        #pragma unroll
        for (int j = 0; j < 4; j++)
            #pragma unroll
            for (int e = 0; e < 4; e++) acc[i][j][e] = 0.0f;

    uint32_t arow[2], brw[2];
    #pragma unroll
    for (int i = 0; i < 2; i++) arow[i] = (uint32_t)(wm + i * 16 + (lid & 15));
    #pragma unroll
    for (int jp = 0; jp < 2; jp++)
        brw[jp] = (uint32_t)(wn + jp * 16 + (lid & 7) + ((lid >> 4) << 3));
    const uint32_t aco = (uint32_t)(lid >> 4);
    const uint32_t bco = (uint32_t)((lid >> 3) & 1);

    #pragma unroll 1
    for (int kc = 0; kc < 2; kc++) {
        const bf16* a_h = Ph + abase + (size_t)lrow * 1024 + kc * 128;
        const bf16* a_l = Pl + abase + (size_t)lrow * 1024 + kc * 128;
        const bf16* b_h = WTh + bbase + (size_t)lrow * 1024 + kc * 128;
        const bf16* b_l = WTl + bbase + (size_t)lrow * 1024 + kc * 128;
        #pragma unroll
        for (int cc = 0; cc < 8; cc++) {
            uint32_t c = lc0 + cc;
            uint32_t d = swz256(lrow, c);
            CPA(sb + d,            a_h + c * 8);
            CPA(sb + GPLB + d,     a_l + c * 8);
            CPA(sb + 2 * GPLB + d, b_h + c * 8);
            CPA(sb + 3 * GPLB + d, b_l + c * 8);
        }
        CPC(); CPW(0);
        __syncthreads();
        #pragma unroll
        for (int ks = 0; ks < 8; ks++) {
            uint32_t ah[2][4], al2[2][4], bh2[4][2], bl2[4][2];
            #pragma unroll
            for (int i = 0; i < 2; i++) {
                uint32_t off = swz256(arow[i], (uint32_t)(ks * 2) + aco);
                LDM4(ah[i], sb + off);
                LDM4(al2[i], sb + GPLB + off);
            }
            #pragma unroll
            for (int jp = 0; jp < 2; jp++) {
                uint32_t off = swz256(brw[jp], (uint32_t)(ks * 2) + bco);
                uint32_t rr[4];
                LDM4(rr, sb + 2 * GPLB + off);
                bh2[2 * jp][0] = rr[0]; bh2[2 * jp][1] = rr[1];
                bh2[2 * jp + 1][0] = rr[2]; bh2[2 * jp + 1][1] = rr[3];
                LDM4(rr, sb + 3 * GPLB + off);
                bl2[2 * jp][0] = rr[0]; bl2[2 * jp][1] = rr[1];
                bl2[2 * jp + 1][0] = rr[2]; bl2[2 * jp + 1][1] = rr[3];
            }
            #pragma unroll
            for (int i = 0; i < 2; i++)
                #pragma unroll
                for (int j = 0; j < 4; j++) mma16(acc[i][j], ah[i], bl2[j]);
            #pragma unroll
            for (int i = 0; i < 2; i++)
                #pragma unroll
                for (int j = 0; j < 4; j++) mma16(acc[i][j], al2[i], bh2[j]);
            #pragma unroll
            for (int i = 0; i < 2; i++)
                #pragma unroll
                for (int j = 0; j < 4; j++) mma16(acc[i][j], ah[i], bh2[j]);
        }
        __syncthreads();
    }

    float* gp = G + (size_t)bh * (DH * DH);
    #pragma unroll
    for (int i = 0; i < 2; i++) {
        #pragma unroll
        for (int j = 0; j < 4; j++) {
            int c = wm + i * 16 + g;
            int d = wn + j * 8 + 2 * t;
            REDADD(gp + c * DH + d,           acc[i][j][0]);
            REDADD(gp + c * DH + d + 1,       acc[i][j][1]);
            REDADD(gp + (c + 8) * DH + d,     acc[i][j][2]);
            REDADD(gp + (c + 8) * DH + d + 1, acc[i][j][3]);
        }
    }
}

// ---------------- split fp32 -> bf16 hi/lo planes ------------------------------
__global__ __launch_bounds__(256)
void split_f32(const float* __restrict__ src, bf16* __restrict__ h, bf16* __restrict__ l)
{
    size_t i = ((size_t)blockIdx.x * 256 + threadIdx.x) * 4;
    float4 v = *(const float4*)(src + i);
    bf16 h0 = __float2bfloat16_rn(v.x), h1 = __float2bfloat16_rn(v.y);
    bf16 h2 = __float2bfloat16_rn(v.z), h3 = __float2bfloat16_rn(v.w);
    bf16 l0 = __float2bfloat16_rn(v.x - __bfloat162float(h0));
    bf16 l1 = __float2bfloat16_rn(v.y - __bfloat162float(h1));
    bf16 l2 = __float2bfloat16_rn(v.z - __bfloat162float(h2));
    bf16 l3 = __float2bfloat16_rn(v.w - __bfloat162float(h3));
    __nv_bfloat162 a, b;
    a.x = h0; a.y = h1; b.x = h2; b.y = h3;
    *(__nv_bfloat162*)(h + i) = a; *(__nv_bfloat162*)(h + i + 2) = b;
    a.x = l0; a.y = l1; b.x = l2; b.y = l3;
    *(__nv_bfloat162*)(l + i) = a; *(__nv_bfloat162*)(l + i + 2) = b;
}

// ---------------- weight prep: z=0 transpose+split Wqk; z=1 split Wv -------------
__global__ __launch_bounds__(256)
void prep_w(const float* __restrict__ Wqk, const float* __restrict__ Wv,
            bf16* __restrict__ WTh, bf16* __restrict__ WTl,
            bf16* __restrict__ WVh, bf16* __restrict__ WVl)
{
    __shared__ float tbuf[32][33];
    int bx = blockIdx.x * 32, by = blockIdx.y * 32;
    int tx = threadIdx.x & 31, ty = threadIdx.x >> 5;
    if (blockIdx.z == 0) {
        #pragma unroll
        for (int i = 0; i < 4; i++) {
            int r = ty + i * 8;
            tbuf[r][tx] = Wqk[(size_t)(by + r) * Dd + bx + tx];
        }
        __syncthreads();
        #pragma unroll
        for (int i = 0; i < 4; i++) {
            int r = ty + i * 8;
            float v = tbuf[tx][r];
            bf16 h = __float2bfloat16_rn(v);
            bf16 l = __float2bfloat16_rn(v - __bfloat162float(h));
            size_t o = (size_t)(bx + r) * Dd + by + tx;
            WTh[o] = h; WTl[o] = l;
        }
    } else {
        #pragma unroll
        for (int i = 0; i < 4; i++) {
            int r = by + ty + i * 8;
            size_t o = (size_t)r * Dd + bx + tx;
            float v = Wv[o];
            bf16 h = __float2bfloat16_rn(v);
            bf16 l = __float2bfloat16_rn(v - __bfloat162float(h));
            WVh[o] = h; WVl[o] = l;
        }
    }
}

// ---------------- build_mT with fused softmax -----------------------------------
__global__ __launch_bounds__(256)
void build_mT(const float* __restrict__ Gr, const float* __restrict__ tau,
              const float* __restrict__ Wout,
              bf16* __restrict__ MTh, bf16* __restrict__ MTl)
{
    const int bh = blockIdx.y;
    const int b = bh >> 4, h = bh & 15;
    const int j0 = blockIdx.x * 64;

    __shared__ float Asm[DH * DH];
    __shared__ float Ws[DH][64];
    __shared__ float diag[DH];

    const int tid = threadIdx.x;
    const float* gp = Gr + (size_t)bh * (DH * DH);
    for (int e = tid; e < DH * DH; e += 256) Asm[e] = gp[e];

    #pragma unroll
    for (int i = 0; i < 4; i++) {
        int idx = tid + i * 256;
        int r = idx >> 4;
        int c4 = (idx & 15) * 4;
        *(float4*)&Ws[r][c4] =
            *(const float4*)(Wout + (size_t)(h * DH + r) * Dd + j0 + c4);
    }
    __syncthreads();
    if (tid < DH) diag[tid] = Asm[tid * DH + tid];
    __syncthreads();

    if (tid < DH) {
        const int c = tid;
        const float tauh = tau[h];
        const float scale = 0.011048543456039806f;   // 1/sqrt(8192)
        const float qc = diag[c];
        float l[DH];
        float mx = -1e30f;
        #pragma unroll 8
        for (int d = 0; d < DH; d++) {
            float v = (2.0f * Asm[c * DH + d] - qc - diag[d]) * scale * tauh;
            l[d] = v;
            mx = fmaxf(mx, v);
        }
        float sum = 0.0f;
        #pragma unroll 8
        for (int d = 0; d < DH; d++) { float e = __expf(l[d] - mx); l[d] = e; sum += e; }
        const float inv = 1.0f / sum;
        #pragma unroll 8
        for (int d = 0; d < DH; d++) Asm[c * DH + d] = l[d] * inv;
    }
    __syncthreads();

    const int tx = tid & 15, ty = tid >> 4;
    float acc[4][4];
    #pragma unroll
    for (int i = 0; i < 4; i++)
        #pragma unroll
        for (int e = 0; e < 4; e++) acc[i][e] = 0.0f;

    for (int c = 0; c < DH; c++) {
        float4 av = *(float4*)&Asm[c * DH + tx * 4];
        #pragma unroll
        for (int i = 0; i < 4; i++) {
            float w = Ws[c][ty * 4 + i];
            acc[i][0] += w * av.x;
            acc[i][1] += w * av.y;
            acc[i][2] += w * av.z;
            acc[i][3] += w * av.w;
        }
    }

    bf16* Mh = MTh + (size_t)b * Dd * Dd;
    bf16* Ml = MTl + (size_t)b * Dd * Dd;
    #pragma unroll
    for (int i = 0; i < 4; i++) {
        int j = j0 + ty * 4 + i;
        size_t o = (size_t)j * Dd + h * DH + tx * 4;
        #pragma unroll
        for (int e = 0; e < 4; e++) {
            float v = acc[i][e];
            bf16 hh = __float2bfloat16_rn(v);
            bf16 ll = __float2bfloat16_rn(v - __bfloat162float(hh));
            Mh[o + e] = hh; Ml[o + e] = ll;
        }
    }
}

// ----------------------------------------------------------------------------------
extern "C" void kernel_launch(void* const* d_in, const int* in_sizes, int n_in,
                              void* d_out, int out_size)
{
    const float* x    = (const float*)d_in[0];
    const float* Wqk  = (const float*)d_in[1];
    const float* Wv   = (const float*)d_in[2];
    const float* Wout = (const float*)d_in[3];
    const float* tau  = (const float*)d_in[4];
    float* out = (float*)d_out;

    void *pxh, *pxl, *pwth, *pwtl, *pwvh, *pwvl, *pacc, *psh, *psl, *pph, *ppl,
         *pmth, *pmtl, *pnth, *pntl;
    cudaGetSymbolAddress(&pxh, g_xh);
    cudaGetSymbolAddress(&pxl, g_xl);
    cudaGetSymbolAddress(&pwth, g_wth);
    cudaGetSymbolAddress(&pwtl, g_wtl);
    cudaGetSymbolAddress(&pwvh, g_wvh);
    cudaGetSymbolAddress(&pwvl, g_wvl);
    cudaGetSymbolAddress(&pacc, g_acc);
    cudaGetSymbolAddress(&psh, g_sh);
    cudaGetSymbolAddress(&psl, g_sl);
    cudaGetSymbolAddress(&pph, g_ph);
    cudaGetSymbolAddress(&ppl, g_pl);
    cudaGetSymbolAddress(&pmth, g_mth);
    cudaGetSymbolAddress(&pmtl, g_mtl);
    cudaGetSymbolAddress(&pnth, g_nth);
    cudaGetSymbolAddress(&pntl, g_ntl);

    bf16 *Xh = (bf16*)pxh, *Xl = (bf16*)pxl;
    bf16 *WTh = (bf16*)pwth, *WTl = (bf16*)pwtl;
    bf16 *WVh = (bf16*)pwvh, *WVl = (bf16*)pwvl;
    float* Acc = (float*)pacc;
    float* Sf  = Acc + SF_OFF;
    float* NTf = Acc + NTF_OFF;
    float* Gr  = Acc + GR_OFF;
    bf16 *Sh = (bf16*)psh, *Sl = (bf16*)psl;
    bf16 *Ph = (bf16*)pph, *Pl = (bf16*)ppl;
    bf16 *MTh = (bf16*)pmth, *MTl = (bf16*)pmtl;
    bf16 *NTh = (bf16*)pnth, *NTl = (bf16*)pntl;

    cudaFuncSetAttribute(mma_gemm<0>, cudaFuncAttributeMaxDynamicSharedMemorySize, SMB);
    cudaFuncSetAttribute(mma_gemm<1>, cudaFuncAttributeMaxDynamicSharedMemorySize, SMB);
    cudaFuncSetAttribute(mma_gemm<3>, cudaFuncAttributeMaxDynamicSharedMemorySize, SMB);
    cudaFuncSetAttribute(syrk_mma,    cudaFuncAttributeMaxDynamicSharedMemorySize, SMB);
    cudaFuncSetAttribute(g_mma,       cudaFuncAttributeMaxDynamicSharedMemorySize, GSMB);

    // 0: one memset for fp32 accumulators, splits, weight prep
    cudaMemsetAsync(Acc, 0, ACC_TOT * sizeof(float));
    split_f32<<<(size_t)Mrows * Dd / 1024, 256>>>(x, Xh, Xl);
    prep_w<<<dim3(32, 32, 2), 256>>>(Wqk, Wv, WTh, WTl, WVh, WVl);
    // 1: S_b = X_b^T X_b (upper-tri + mirror, token split-K=4)
    syrk_mma<<<dim3(144, 1, 2), 256, SMB>>>(Xh, Xl, Sf);
    // 2: split S
    split_f32<<<(size_t)Bq * Dd * Dd / 1024, 256>>>(Sf, Sh, Sl);
    // 3: P_b = WT @ S_b
    mma_gemm<3><<<dim3(8, 8, 2), 256, SMB>>>(WTh, WTl, 0, Sh, Sl, (size_t)Dd * Dd,
                                             nullptr, nullptr, Ph, Pl, (size_t)Dd * Dd,
                                             8, 32);
    // 4: G_bh = P_h @ WT_h^T
    g_mma<<<dim3(4, 32), 128, GSMB>>>(Ph, Pl, WTh, WTl, Gr);
    // 5: softmax + fold attn into W_out (fused)
    build_mT<<<dim3(16, 32), 256>>>(Gr, tau, Wout, MTh, MTl);
    // 6: NT_b = MT_b @ Wv^T  (split-K=4)
    mma_gemm<1><<<dim3(32, 8, 2), 256, SMB>>>(MTh, MTl, (size_t)Dd * Dd,
                                              WVh, WVl, 0,
                                              NTf, NTf + (size_t)Dd * Dd,
                                              nullptr, nullptr, 0, 8, 8);
    // 7: split NT
    split_f32<<<(size_t)Bq * Dd * Dd / 1024, 256>>>(NTf, NTh, NTl);
    // 8: out_b = X_b @ N_b  (plain store, no split-K)
    mma_gemm<0><<<dim3(8, 64, 2), 256, SMB>>>(Xh, Xl, (size_t)Nt * Dd,
                                              NTh, NTl, (size_t)Dd * Dd,
                                              out, out + (size_t)Nt * Dd,
                                              nullptr, nullptr, 0, 8, 32);
}